// round 9
// baseline (speedup 1.0000x reference)
#include <cuda_runtime.h>
#include <cstdint>

#define BB 64
#define NN 512
#define HH 128
#define NCOG 72
#define NRB 72

__device__ __align__(16) float g_wc[(size_t)BB * NN * NN];  // compacted w rows
__device__ int      g_jlist[BB][NN];
__device__ int      g_jcnt[BB];
__device__ unsigned g_maxbits;

// ---------------------------------------------------------------------------
__global__ void k_zero_out(float4* __restrict__ out, int n4) {
    int idx = blockIdx.x * blockDim.x + threadIdx.x;
    int stride = gridDim.x * blockDim.x;
    float4 z = make_float4(0.f, 0.f, 0.f, 0.f);
    for (int i = idx; i < n4; i += stride) out[i] = z;
}

// ---------------------------------------------------------------------------
__global__ void k_compact(const float* __restrict__ mask) {
    int b = blockIdx.x;
    int j = threadIdx.x;
    if (b == 0 && j == 0) g_maxbits = 0u;

    bool act = (mask[b * NN + j] != 0.0f);
    unsigned ball = __ballot_sync(0xffffffffu, act);

    __shared__ int wcnt[16], wbase[16];
    int warp = j >> 5, lane = j & 31;
    if (lane == 0) wcnt[warp] = __popc(ball);
    __syncthreads();
    if (j == 0) {
        int s = 0;
        for (int w = 0; w < 16; w++) { wbase[w] = s; s += wcnt[w]; }
        g_jcnt[b] = s;
    }
    __syncthreads();
    if (act) {
        int pos = wbase[warp] + __popc(ball & ((1u << lane) - 1u));
        g_jlist[b][pos] = j;
    }
}

// ---------------------------------------------------------------------------
// Build compacted w rows: 8 rows per block (s_pos built ONCE per block).
// Dense int4/float4 reads, relu, scatter-stage to smem, compact float4 writes.
// ---------------------------------------------------------------------------
__global__ void __launch_bounds__(128) k_build_w(
    const int*   __restrict__ rmat,
    const float* __restrict__ dmat,
    const int*   __restrict__ cog,
    const float* __restrict__ domain)
{
    int b   = blockIdx.y;
    int cnt = g_jcnt[b];
    int ip_base = blockIdx.x * 8;
    if (ip_base >= cnt) return;

    __shared__ int s_pos[NN];
    __shared__ __align__(16) float s_stage[NN];
    __shared__ int s_rows[8];
    __shared__ float smax[4];
    int t = threadIdx.x;

    #pragma unroll
    for (int q = 0; q < 4; q++) {
        s_pos[t + q * 128]   = -1;
        s_stage[t + q * 128] = 0.f;
    }
    __syncthreads();
    #pragma unroll
    for (int q = 0; q < 4; q++) {
        int jc = t + q * 128;
        if (jc < cnt) s_pos[g_jlist[b][jc]] = jc;
    }
    if (t < 8) {
        int ip = ip_base + t;
        s_rows[t] = (ip < cnt) ? g_jlist[b][ip] : -1;
    }
    __syncthreads();

    int cnt32 = (cnt + 31) & ~31;
    int nrows = min(8, cnt - ip_base);
    int j0 = t * 4;
    float lm = 0.f;

    for (int rr = 0; rr < nrows; rr++) {
        int i = s_rows[rr];
        size_t src = ((size_t)(b * NN + i)) * NN;

        int4   rv = *(const int4*)(rmat + src + j0);
        int4   cv = *(const int4*)(cog  + src + j0);
        float4 dv = *(const float4*)(dmat + src + j0);

        float w0 = fmaxf(__ldg(domain + cv.x * NRB + rv.x) - dv.x, 0.f);
        float w1 = fmaxf(__ldg(domain + cv.y * NRB + rv.y) - dv.y, 0.f);
        float w2 = fmaxf(__ldg(domain + cv.z * NRB + rv.z) - dv.z, 0.f);
        float w3 = fmaxf(__ldg(domain + cv.w * NRB + rv.w) - dv.w, 0.f);

        int p0 = s_pos[j0 + 0], p1 = s_pos[j0 + 1], p2 = s_pos[j0 + 2], p3 = s_pos[j0 + 3];
        if (p0 >= 0) { s_stage[p0] = w0; lm = fmaxf(lm, w0); }
        if (p1 >= 0) { s_stage[p1] = w1; lm = fmaxf(lm, w1); }
        if (p2 >= 0) { s_stage[p2] = w2; lm = fmaxf(lm, w2); }
        if (p3 >= 0) { s_stage[p3] = w3; lm = fmaxf(lm, w3); }
        __syncthreads();    // stage complete

        size_t dst = ((size_t)(b * NN + ip_base + rr)) * NN;
        if (j0 < cnt32)
            *(float4*)(g_wc + dst + j0) = *(const float4*)(s_stage + j0);
        __syncthreads();    // copy done before next scatter overwrites
    }

    #pragma unroll
    for (int off = 16; off; off >>= 1)
        lm = fmaxf(lm, __shfl_xor_sync(0xffffffffu, lm, off));
    if ((t & 31) == 0) smax[t >> 5] = lm;
    __syncthreads();
    if (t == 0) {
        float bm = fmaxf(fmaxf(smax[0], smax[1]), fmaxf(smax[2], smax[3]));
        atomicMax(&g_maxbits, __float_as_uint(bm));
    }
}

// ---------------------------------------------------------------------------
// Compacted GEMM. Tile 32i x 128h, 128 threads, per-thread 4i x 8h.
// tx = tid&15 -> h = [tx*4,+4) and [64+tx*4,+4); ty = tid>>4 (0..7) -> rows ty*4..+3.
// Per warp-kk: 4 h-wavefronts + 4 w-broadcasts vs 32 FFMA (16cy) -> FFMA-bound.
// Grid (16, 64) -> ~512 working blocks.
// ---------------------------------------------------------------------------
__global__ void __launch_bounds__(128, 6) k_gemm(
    const float* __restrict__ h_t,
    float*       __restrict__ out)
{
    int b   = blockIdx.y;
    int cnt = g_jcnt[b];
    int ip0 = blockIdx.x * 32;
    if (ip0 >= cnt) return;
    int cnt32 = (cnt + 31) & ~31;

    int tid = threadIdx.x;
    int tx  = tid & 15;
    int ty  = tid >> 4;

    __shared__ __align__(16) float sW[32][36];   // 144B rows: aligned; Δ4-row warp pairs conflict-free
    __shared__ __align__(16) float sH[32][128];
    __shared__ int s_jl[NN];
    __shared__ int s_il[32];

    #pragma unroll
    for (int q = 0; q < 4; q++) {
        int jc = tid + q * 128;
        s_jl[jc] = (jc < cnt) ? g_jlist[b][jc] : 0;
    }
    if (tid < 32) {
        int ip = ip0 + tid;
        s_il[tid] = (ip < cnt) ? g_jlist[b][ip] : 0;
    }

    float acc[4][8];
    #pragma unroll
    for (int a = 0; a < 4; a++)
        #pragma unroll
        for (int c = 0; c < 8; c++) acc[a][c] = 0.f;

    const float* hb = h_t + (size_t)b * HH;
    const float* wb = g_wc + ((size_t)b * NN + ip0) * NN;

    for (int kc0 = 0; kc0 < cnt32; kc0 += 32) {
        __syncthreads();

        // W tile 32x32: 256 float4, 2 per thread.
        #pragma unroll
        for (int rep = 0; rep < 2; rep++) {
            int e  = rep * 128 + tid;
            int ii = e >> 3;
            int kq = e & 7;
            float4 v = make_float4(0.f, 0.f, 0.f, 0.f);
            if (ip0 + ii < cnt)
                v = *(const float4*)(wb + (size_t)ii * NN + kc0 + kq * 4);
            *(float4*)(&sW[ii][kq * 4]) = v;
        }
        // H tile 32x128 gathered rows: 1024 float4, 8 per thread (coalesced 512B rows).
        #pragma unroll
        for (int rep = 0; rep < 8; rep++) {
            int e  = rep * 128 + tid;
            int kk = e >> 5;
            int h4 = e & 31;
            int j  = s_jl[kc0 + kk];
            float4 hv = *(const float4*)(hb + (size_t)j * (BB * HH) + h4 * 4);
            *(float4*)(&sH[kk][h4 * 4]) = hv;
        }
        __syncthreads();

        #pragma unroll
        for (int kk = 0; kk < 32; kk++) {
            float4 h0 = *(const float4*)(&sH[kk][tx * 4]);
            float4 h1 = *(const float4*)(&sH[kk][64 + tx * 4]);
            #pragma unroll
            for (int a = 0; a < 4; a++) {
                float wv = sW[ty * 4 + a][kk];
                acc[a][0] = fmaf(wv, h0.x, acc[a][0]);
                acc[a][1] = fmaf(wv, h0.y, acc[a][1]);
                acc[a][2] = fmaf(wv, h0.z, acc[a][2]);
                acc[a][3] = fmaf(wv, h0.w, acc[a][3]);
                acc[a][4] = fmaf(wv, h1.x, acc[a][4]);
                acc[a][5] = fmaf(wv, h1.y, acc[a][5]);
                acc[a][6] = fmaf(wv, h1.z, acc[a][6]);
                acc[a][7] = fmaf(wv, h1.w, acc[a][7]);
            }
        }
    }

    float inv = 1.0f / __uint_as_float(g_maxbits);
    #pragma unroll
    for (int a = 0; a < 4; a++) {
        int ipl = ty * 4 + a;
        if (ip0 + ipl < cnt) {
            int i = s_il[ipl];
            float* op = out + ((size_t)(b * NN + i)) * HH;
            float4 o0 = make_float4(acc[a][0] * inv, acc[a][1] * inv,
                                    acc[a][2] * inv, acc[a][3] * inv);
            float4 o1 = make_float4(acc[a][4] * inv, acc[a][5] * inv,
                                    acc[a][6] * inv, acc[a][7] * inv);
            *(float4*)(op + tx * 4)      = o0;
            *(float4*)(op + 64 + tx * 4) = o1;
        }
    }
}

// ---------------------------------------------------------------------------
extern "C" void kernel_launch(void* const* d_in, const int* in_sizes, int n_in,
                              void* d_out, int out_size)
{
    const float* h_t    = (const float*)d_in[0];
    const int*   r_mat  = (const int*)  d_in[1];
    const float* d_mat  = (const float*)d_in[2];
    const float* mask   = (const float*)d_in[3];
    const int*   cog    = (const int*)  d_in[4];
    const float* domain = (const float*)d_in[5];
    float* out = (float*)d_out;

    k_zero_out<<<1024, 256>>>((float4*)out, out_size / 4);
    k_compact<<<BB, NN>>>(mask);
    dim3 g1(NN / 8, BB);
    k_build_w<<<g1, 128>>>(r_mat, d_mat, cog, domain);
    dim3 g2(NN / 32, BB);
    k_gemm<<<g2, 128>>>(h_t, out);
}